// round 12
// baseline (speedup 1.0000x reference)
#include <cuda_runtime.h>
#include <math_constants.h>

typedef unsigned long long ull;

#define NOBJ    16
#define P       4096
#define THREADS 512
#define QPT     2                    // queries per thread
#define CHUNK   (THREADS*QPT)        // 1024 queries per block
#define NCHUNK  (P/CHUNK)            // 4 chunks per (object, direction)
#define NPAIR   (P/2)                // 2048 packed target pairs
#define GRIDSZ  (2*NOBJ*NCHUNK)      // 128 blocks
#define EPSF    1e-12f

// Deterministic scratch: every slot rewritten on every launch.
__device__ float g_partial[2 * NOBJ * NCHUNK];
__device__ float g_masksum[NOBJ * NCHUNK];
__device__ unsigned int g_arrive;    // 0 at launch; last block resets it

__device__ __forceinline__ ull ffma2(ull a, ull b, ull c) {
    ull r;
    asm("fma.rn.f32x2 %0, %1, %2, %3;" : "=l"(r) : "l"(a), "l"(b), "l"(c));
    return r;
}
__device__ __forceinline__ float2 unpk(ull x) {
    float2 f;
    asm("mov.b64 {%0, %1}, %2;" : "=f"(f.x), "=f"(f.y) : "l"(x));
    return f;
}
__device__ __forceinline__ ull pk(float lo, float hi) {
    ull r;
    asm("mov.b64 %0, {%1, %2};" : "=l"(r) : "f"(lo), "f"(hi));
    return r;
}

// Fused kernel: per (query-chunk, object, direction) block computes
// sum over queries of sqrt(max(min_j dist2, EPS)); dir=1 blocks also
// accumulate the s2 mask sum. Last block to arrive does the final
// fixed-order combine and writes the scalar output.
// dist2(i,j) = x2_i + (w_j - x0*u_j - x1*v_j), u=2*t0, v=2*t1, w=|t|^2.
// 512 threads -> 16 warps/SM (4 per SMSP) for latency hiding;
// zero static shared: 48 KB dynamic exactly, flag lives inside it.
__global__ __launch_bounds__(THREADS, 1)
void chamfer_fused(const float* __restrict__ s1, const float* __restrict__ s2,
                   float* __restrict__ out) {
    extern __shared__ ull dsm[];                 // 48 KB dynamic
    ulonglong2* sUV = (ulonglong2*)dsm;          // [NPAIR] : 32 KB  (u,v packed)
    ull*        sW  = dsm + 2 * NPAIR;           // [NPAIR] : 16 KB  (w packed)

    const int chunk = blockIdx.x;
    const int n     = blockIdx.y;
    const int dir   = blockIdx.z;
    const int tid   = threadIdx.x;

    const float* qb = (dir == 0 ? s1 : s2) + (size_t)n * P * 2;
    const float* tb = (dir == 0 ? s2 : s1) + (size_t)n * P * 2;

    // Load + transform targets into shared (packed over j-pairs).
    const float4* t4 = (const float4*)tb;
    for (int p = tid; p < NPAIR; p += THREADS) {
        float4 t = t4[p];                        // (t0.x, t0.y, t1.x, t1.y)
        ulonglong2 uv;
        uv.x = pk(2.0f * t.x, 2.0f * t.z);       // u = 2*t0
        uv.y = pk(2.0f * t.y, 2.0f * t.w);       // v = 2*t1
        sUV[p] = uv;
        sW[p]  = pk(t.x * t.x + t.y * t.y, t.z * t.z + t.w * t.w);
    }

    // Load this thread's queries; dir=1 also accumulates mask partial.
    float x2[QPT];
    ull   nx0[QPT], nx1[QPT];
    float msum = 0.0f;
#pragma unroll
    for (int k = 0; k < QPT; k++) {
        int qi = chunk * CHUNK + k * THREADS + tid;
        float2 q = ((const float2*)qb)[qi];
        x2[k]  = q.x * q.x + q.y * q.y;
        nx0[k] = pk(-q.x, -q.x);
        nx1[k] = pk(-q.y, -q.y);
        if (dir == 1) msum += q.x + q.y;
    }
    __syncthreads();

    float mn[QPT][4];
#pragma unroll
    for (int k = 0; k < QPT; k++)
#pragma unroll
        for (int s = 0; s < 4; s++) mn[k][s] = CUDART_INF_F;

    // Main loop: 2048 packed pairs, unroll 8 (4 min-slots reused).
    // Per pair per query: 2 FFMA2 (fma pipe) + 2 FMNMX (alu pipe);
    // 2 broadcast LDS per pair shared across both queries.
    for (int p = 0; p < NPAIR; p += 8) {
#pragma unroll
        for (int s = 0; s < 8; s++) {
            ulonglong2 uv = sUV[p + s];
            ull        w2 = sW[p + s];
#pragma unroll
            for (int k = 0; k < QPT; k++) {
                ull e = ffma2(nx1[k], uv.y, ffma2(nx0[k], uv.x, w2));
                float2 f = unpk(e);
                mn[k][s & 3] = fminf(mn[k][s & 3], fminf(f.x, f.y));
            }
        }
    }

    float lsum = 0.0f;
#pragma unroll
    for (int k = 0; k < QPT; k++) {
        float m = fminf(fminf(mn[k][0], mn[k][1]), fminf(mn[k][2], mn[k][3]));
        lsum += sqrtf(fmaxf(x2[k] + m, EPSF));
    }

    // Deterministic block reduction (reuse dynamic smem; flag lives there too).
    __syncthreads();
    float* red  = (float*)dsm;                    // [0 .. 2*THREADS)
    int*   flag = (int*)(red + 2 * THREADS);
    red[tid]           = lsum;
    red[THREADS + tid] = msum;
    __syncthreads();
    for (int s = THREADS / 2; s > 0; s >>= 1) {
        if (tid < s) {
            red[tid]           += red[tid + s];
            red[THREADS + tid] += red[THREADS + tid + s];
        }
        __syncthreads();
    }

    if (tid == 0) {
        g_partial[(dir * NOBJ + n) * NCHUNK + chunk] = red[0];
        if (dir == 1) g_masksum[n * NCHUNK + chunk] = red[THREADS];
        __threadfence();
        flag[0] = (atomicAdd(&g_arrive, 1u) == GRIDSZ - 1) ? 1 : 0;
    }
    __syncthreads();

    // Last-arriving block: fixed-order final combine (deterministic).
    if (flag[0] && tid < 16) {
        __threadfence();                          // acquire side of release/arrive
        float d = 0.0f, ms = 0.0f;
#pragma unroll
        for (int c = 0; c < NCHUNK; c++) {
            d  += g_partial[(0 * NOBJ + tid) * NCHUNK + c];
            d  += g_partial[(1 * NOBJ + tid) * NCHUNK + c];
            ms += g_masksum[tid * NCHUNK + c];
        }
        float cost = d * (0.5f / (float)P);       // 0.5*(mean d1 + mean d2)
        float val  = (ms >= 0.0f) ? cost : 0.0f;
#pragma unroll
        for (int o = 8; o > 0; o >>= 1)
            val += __shfl_xor_sync(0xffffu, val, o);
        if (tid == 0) {
            out[0] = val * (1.0f / (float)NOBJ);
            g_arrive = 0u;                        // reset for next graph replay
        }
    }
}

extern "C" void kernel_launch(void* const* d_in, const int* in_sizes, int n_in,
                              void* d_out, int out_size) {
    const float* s1 = (const float*)d_in[0];
    const float* s2 = (const float*)d_in[1];
    dim3 grid(NCHUNK, NOBJ, 2);
    size_t smem = 3 * NPAIR * sizeof(ull);        // 49152 bytes, no static smem
    chamfer_fused<<<grid, THREADS, smem>>>(s1, s2, (float*)d_out);
}

// round 13
// speedup vs baseline: 1.0329x; 1.0329x over previous
#include <cuda_runtime.h>
#include <math_constants.h>

typedef unsigned long long ull;

#define NOBJ    16
#define P       4096
#define THREADS 512
#define QPT     2                    // queries per thread
#define CHUNK   (THREADS*QPT)        // 1024 queries per block
#define NCHUNK  (P/CHUNK)            // 4 chunks per (object, direction)
#define NPAIR   (P/2)                // 2048 packed target pairs
#define GRIDSZ  (2*NOBJ*NCHUNK)      // 128 blocks
#define EPSF    1e-12f

// Deterministic scratch: every slot rewritten on every launch.
__device__ float g_partial[2 * NOBJ * NCHUNK];
__device__ float g_masksum[NOBJ * NCHUNK];
__device__ unsigned int g_arrive;    // 0 at launch; last block resets it

__device__ __forceinline__ ull ffma2(ull a, ull b, ull c) {
    ull r;
    asm("fma.rn.f32x2 %0, %1, %2, %3;" : "=l"(r) : "l"(a), "l"(b), "l"(c));
    return r;
}
__device__ __forceinline__ float2 unpk(ull x) {
    float2 f;
    asm("mov.b64 {%0, %1}, %2;" : "=f"(f.x), "=f"(f.y) : "l"(x));
    return f;
}
__device__ __forceinline__ ull pk(float lo, float hi) {
    ull r;
    asm("mov.b64 %0, {%1, %2};" : "=l"(r) : "f"(lo), "f"(hi));
    return r;
}

// Fused kernel: per (query-chunk, object, direction) block computes
// sum over queries of sqrt(max(min_j dist2, EPS)); dir=1 blocks also
// accumulate the s2 mask sum. Last block to arrive does the final
// fixed-order combine and writes the scalar output.
// dist2(i,j) = x2_i + (w_j - x0*u_j - x1*v_j), u=2*t0, v=2*t1, w=|t|^2.
// Main loop is explicitly software-pipelined: register double-buffer of
// 4 target-pairs; prefetch next batch while computing current batch.
__global__ __launch_bounds__(THREADS, 1)
void chamfer_fused(const float* __restrict__ s1, const float* __restrict__ s2,
                   float* __restrict__ out) {
    extern __shared__ ull dsm[];                 // 48 KB dynamic, no static smem
    ulonglong2* sUV = (ulonglong2*)dsm;          // [NPAIR] : 32 KB  (u,v packed)
    ull*        sW  = dsm + 2 * NPAIR;           // [NPAIR] : 16 KB  (w packed)

    const int chunk = blockIdx.x;
    const int n     = blockIdx.y;
    const int dir   = blockIdx.z;
    const int tid   = threadIdx.x;

    const float* qb = (dir == 0 ? s1 : s2) + (size_t)n * P * 2;
    const float* tb = (dir == 0 ? s2 : s1) + (size_t)n * P * 2;

    // Load + transform targets into shared (packed over j-pairs).
    const float4* t4 = (const float4*)tb;
    for (int p = tid; p < NPAIR; p += THREADS) {
        float4 t = t4[p];                        // (t0.x, t0.y, t1.x, t1.y)
        ulonglong2 uv;
        uv.x = pk(2.0f * t.x, 2.0f * t.z);       // u = 2*t0
        uv.y = pk(2.0f * t.y, 2.0f * t.w);       // v = 2*t1
        sUV[p] = uv;
        sW[p]  = pk(t.x * t.x + t.y * t.y, t.z * t.z + t.w * t.w);
    }

    // Load this thread's queries; dir=1 also accumulates mask partial.
    float x2[QPT];
    ull   nx0[QPT], nx1[QPT];
    float msum = 0.0f;
#pragma unroll
    for (int k = 0; k < QPT; k++) {
        int qi = chunk * CHUNK + k * THREADS + tid;
        float2 q = ((const float2*)qb)[qi];
        x2[k]  = q.x * q.x + q.y * q.y;
        nx0[k] = pk(-q.x, -q.x);
        nx1[k] = pk(-q.y, -q.y);
        if (dir == 1) msum += q.x + q.y;
    }
    __syncthreads();

    float mn[QPT][4];
#pragma unroll
    for (int k = 0; k < QPT; k++)
#pragma unroll
        for (int s = 0; s < 4; s++) mn[k][s] = CUDART_INF_F;

    // Software-pipelined main loop: double-buffered 4-pair batches.
    // Per batch: 8 LDS prefetch (next) + 32 math (current) -> 32 issue
    // cycles of independent math cover the 29-cycle LDS latency.
    ulonglong2 uvb[2][4];
    ull        wb[2][4];
#pragma unroll
    for (int s = 0; s < 4; s++) { uvb[0][s] = sUV[s]; wb[0][s] = sW[s]; }

    for (int p = 0; p < NPAIR; p += 8) {
        // Prefetch batch B (pairs p+4 .. p+7) into buffer 1.
#pragma unroll
        for (int s = 0; s < 4; s++) {
            uvb[1][s] = sUV[p + 4 + s];
            wb[1][s]  = sW[p + 4 + s];
        }
        // Compute batch A (buffer 0).
#pragma unroll
        for (int s = 0; s < 4; s++) {
#pragma unroll
            for (int k = 0; k < QPT; k++) {
                ull e = ffma2(nx1[k], uvb[0][s].y, ffma2(nx0[k], uvb[0][s].x, wb[0][s]));
                float2 f = unpk(e);
                mn[k][s] = fminf(mn[k][s], fminf(f.x, f.y));
            }
        }
        // Prefetch next batch A (pairs p+8 ..) into buffer 0 (wrap-safe).
        int np = (p + 8 < NPAIR) ? (p + 8) : 0;
#pragma unroll
        for (int s = 0; s < 4; s++) {
            uvb[0][s] = sUV[np + s];
            wb[0][s]  = sW[np + s];
        }
        // Compute batch B (buffer 1).
#pragma unroll
        for (int s = 0; s < 4; s++) {
#pragma unroll
            for (int k = 0; k < QPT; k++) {
                ull e = ffma2(nx1[k], uvb[1][s].y, ffma2(nx0[k], uvb[1][s].x, wb[1][s]));
                float2 f = unpk(e);
                mn[k][s] = fminf(mn[k][s], fminf(f.x, f.y));
            }
        }
    }

    float lsum = 0.0f;
#pragma unroll
    for (int k = 0; k < QPT; k++) {
        float m = fminf(fminf(mn[k][0], mn[k][1]), fminf(mn[k][2], mn[k][3]));
        lsum += sqrtf(fmaxf(x2[k] + m, EPSF));
    }

    // Deterministic block reduction (reuse dynamic smem; flag lives there too).
    __syncthreads();
    float* red  = (float*)dsm;                    // [0 .. 2*THREADS)
    int*   flag = (int*)(red + 2 * THREADS);
    red[tid]           = lsum;
    red[THREADS + tid] = msum;
    __syncthreads();
    for (int s = THREADS / 2; s > 0; s >>= 1) {
        if (tid < s) {
            red[tid]           += red[tid + s];
            red[THREADS + tid] += red[THREADS + tid + s];
        }
        __syncthreads();
    }

    if (tid == 0) {
        g_partial[(dir * NOBJ + n) * NCHUNK + chunk] = red[0];
        if (dir == 1) g_masksum[n * NCHUNK + chunk] = red[THREADS];
        __threadfence();
        flag[0] = (atomicAdd(&g_arrive, 1u) == GRIDSZ - 1) ? 1 : 0;
    }
    __syncthreads();

    // Last-arriving block: fixed-order final combine (deterministic).
    if (flag[0] && tid < 16) {
        __threadfence();                          // acquire side of release/arrive
        float d = 0.0f, ms = 0.0f;
#pragma unroll
        for (int c = 0; c < NCHUNK; c++) {
            d  += g_partial[(0 * NOBJ + tid) * NCHUNK + c];
            d  += g_partial[(1 * NOBJ + tid) * NCHUNK + c];
            ms += g_masksum[tid * NCHUNK + c];
        }
        float cost = d * (0.5f / (float)P);       // 0.5*(mean d1 + mean d2)
        float val  = (ms >= 0.0f) ? cost : 0.0f;
#pragma unroll
        for (int o = 8; o > 0; o >>= 1)
            val += __shfl_xor_sync(0xffffu, val, o);
        if (tid == 0) {
            out[0] = val * (1.0f / (float)NOBJ);
            g_arrive = 0u;                        // reset for next graph replay
        }
    }
}

extern "C" void kernel_launch(void* const* d_in, const int* in_sizes, int n_in,
                              void* d_out, int out_size) {
    const float* s1 = (const float*)d_in[0];
    const float* s2 = (const float*)d_in[1];
    dim3 grid(NCHUNK, NOBJ, 2);
    size_t smem = 3 * NPAIR * sizeof(ull);        // 49152 bytes, no static smem
    chamfer_fused<<<grid, THREADS, smem>>>(s1, s2, (float*)d_out);
}